// round 3
// baseline (speedup 1.0000x reference)
#include <cuda_runtime.h>
#include <math.h>

#define NPTS   2048
#define NGAB   2
#define IMG_H  512
#define IMG_W  512
#define HW     (IMG_H * IMG_W)
#define RENDER_SZ (3 * HW)
#define ALPHA_THRESH (1.0f / 255.0f)

#define TILE     16
#define TILES_X  (IMG_W / TILE)   // 32
#define TILES_Y  (IMG_H / TILE)   // 32
#define NTILES   (TILES_X * TILES_Y)  // 1024
#define CAP      2048             // worst-case list capacity (all points)

// Point data, 4 x float4 per point:
//  [0] = {x, y, ca, cb}
//  [1] = {cc, op, Tcut, r}
//  [2] = {g, b, fx0, fy0}
//  [3] = {fx1, fy1, w0, w1}
__device__ float4 g_pts[NPTS * 4];
__device__ int    g_tile_cnt[NTILES];          // zero-init; render restores zeros
__device__ int    g_tile_list[NTILES * CAP];

__device__ __forceinline__ float sigmoidf_(float v) {
    return 1.0f / (1.0f + __expf(-v));
}

// One thread per point: prep + bin into tile lists + radii/visibility.
__global__ void prep_bin_kernel(const float* __restrict__ xyz,
                                const float* __restrict__ cov2d,
                                const float* __restrict__ fdc,
                                const float* __restrict__ opac,
                                const float* __restrict__ gfreq,
                                const float* __restrict__ gwt,
                                float* __restrict__ out, int out_size) {
    int i = blockIdx.x * blockDim.x + threadIdx.x;
    if (i >= NPTS) return;

    float sxx = cov2d[3 * i + 0] + 0.5f;
    float sxy = cov2d[3 * i + 1];
    float syy = cov2d[3 * i + 2] + 0.5f;
    float det = sxx * syy - sxy * sxy;
    bool valid = det > 1e-8f;
    float det_s = valid ? det : 1.0f;
    float ca =  syy / det_s;
    float cb = -sxy / det_s;
    float cc =  sxx / det_s;

    float mid = 0.5f * (sxx + syy);
    float lam = mid + sqrtf(fmaxf(mid * mid - det, 0.1f));
    int radii = valid ? (int)ceilf(3.0f * sqrtf(lam)) : 0;

    if (out_size >= RENDER_SZ + NPTS)
        out[RENDER_SZ + i] = (float)radii;
    if (out_size >= RENDER_SZ + 2 * NPTS)
        out[RENDER_SZ + NPTS + i] = (radii > 0) ? 1.0f : 0.0f;

    float x = xyz[2 * i + 0];
    float y = xyz[2 * i + 1];
    float op = opac[i];

    float4 p0, p1, p2, p3;
    p0.x = x; p0.y = y; p0.z = ca; p0.w = cb;
    p1.x = cc; p1.y = op;
    float Tcut = __logf(fmaxf(op, 1e-30f) * 255.0f);  // alpha>=1/255 <=> sigma<=Tcut
    p1.z = Tcut;
    p1.w = sigmoidf_(fdc[3 * i + 0]);
    p2.x = sigmoidf_(fdc[3 * i + 1]);
    p2.y = sigmoidf_(fdc[3 * i + 2]);
    p2.z = __expf(gfreq[(i * NGAB + 0) * 2 + 0]);
    p2.w = __expf(gfreq[(i * NGAB + 0) * 2 + 1]);
    p3.x = __expf(gfreq[(i * NGAB + 1) * 2 + 0]);
    p3.y = __expf(gfreq[(i * NGAB + 1) * 2 + 1]);
    p3.z = sigmoidf_(gwt[i * NGAB + 0]);
    p3.w = sigmoidf_(gwt[i * NGAB + 1]);

    g_pts[i * 4 + 0] = p0;
    g_pts[i * 4 + 1] = p1;
    g_pts[i * 4 + 2] = p2;
    g_pts[i * 4 + 3] = p3;

    if (!valid || Tcut <= 0.0f) return;

    // Conservative support bbox (superset of {alpha >= 1/255}) + 1px slop.
    float dxm = sqrtf(2.0f * Tcut * sxx) + 1.0f;
    float dym = sqrtf(2.0f * Tcut * syy) + 1.0f;
    int x0 = max(0, (int)floorf(x - dxm - 0.5f));
    int x1 = min(IMG_W - 1, (int)ceilf(x + dxm - 0.5f));
    int y0 = max(0, (int)floorf(y - dym - 0.5f));
    int y1 = min(IMG_H - 1, (int)ceilf(y + dym - 0.5f));
    if (x0 > x1 || y0 > y1) return;

    int tx0 = x0 / TILE, tx1 = x1 / TILE;
    int ty0 = y0 / TILE, ty1 = y1 / TILE;
    for (int ty = ty0; ty <= ty1; ty++)
        for (int tx = tx0; tx <= tx1; tx++) {
            int t = ty * TILES_X + tx;
            int idx = atomicAdd(&g_tile_cnt[t], 1);
            if (idx < CAP) g_tile_list[t * CAP + idx] = i;
        }
}

// One block per 16x16 tile, one thread per pixel. Gather over the tile's
// list, accumulate in registers, clamp, write each output pixel exactly once.
__global__ void render_kernel(float* __restrict__ out) {
    int tile = blockIdx.x;
    int tx = tile % TILES_X, ty = tile / TILES_X;
    int lx = threadIdx.x % TILE, ly = threadIdx.x / TILE;
    int px = tx * TILE + lx;
    int py = ty * TILE + ly;
    float fpx = (float)px + 0.5f;
    float fpy = (float)py + 0.5f;

    __shared__ int s_cnt;
    if (threadIdx.x == 0) {
        s_cnt = g_tile_cnt[tile];
        g_tile_cnt[tile] = 0;       // restore zero-invariant for next replay
    }
    __syncthreads();
    int cnt = min(s_cnt, CAP);
    const int* list = &g_tile_list[tile * CAP];

    float accR = 0.0f, accG = 0.0f, accB = 0.0f;

    for (int j = 0; j < cnt; j++) {
        int g = list[j];                      // uniform across block
        float4 p0 = g_pts[g * 4 + 0];
        float4 p1 = g_pts[g * 4 + 1];
        float dx = fpx - p0.x;
        float dy = fpy - p0.y;
        float sigma = 0.5f * (p0.z * dx * dx + p1.x * dy * dy) + p0.w * (dx * dy);
        // Guaranteed alpha < 1/255 when sigma > Tcut + margin (margin >> fp noise).
        if (sigma > p1.z + 0.02f) continue;
        float alpha = fminf(p1.y * __expf(-sigma), 0.999f);
        if (alpha < ALPHA_THRESH) continue;   // exact reference threshold
        float4 p2 = g_pts[g * 4 + 2];
        float4 p3 = g_pts[g * 4 + 3];
        float arg0 = p2.z * dx + p2.w * dy;
        float arg1 = p3.x * dx + p3.y * dy;
        float mod = 1.0f + p3.z * __cosf(arg0) + p3.w * __cosf(arg1);
        float wgt = alpha * mod;
        accR += wgt * p1.w;
        accG += wgt * p2.x;
        accB += wgt * p2.y;
    }

    int pix = py * IMG_W + px;
    out[pix]          = fminf(fmaxf(accR, 0.0f), 1.0f);
    out[HW + pix]     = fminf(fmaxf(accG, 0.0f), 1.0f);
    out[2 * HW + pix] = fminf(fmaxf(accB, 0.0f), 1.0f);
}

extern "C" void kernel_launch(void* const* d_in, const int* in_sizes, int n_in,
                              void* d_out, int out_size) {
    const float* xyz   = (const float*)d_in[0];
    const float* cov2d = (const float*)d_in[1];
    const float* fdc   = (const float*)d_in[2];
    const float* opac  = (const float*)d_in[3];
    const float* gfreq = (const float*)d_in[4];
    const float* gwt   = (const float*)d_in[5];
    float* out = (float*)d_out;

    prep_bin_kernel<<<NPTS / 256, 256>>>(xyz, cov2d, fdc, opac, gfreq, gwt, out, out_size);
    render_kernel<<<NTILES, TILE * TILE>>>(out);
}

// round 4
// speedup vs baseline: 1.8470x; 1.8470x over previous
#include <cuda_runtime.h>
#include <math.h>

#define NPTS   2048
#define NGAB   2
#define IMG_H  512
#define IMG_W  512
#define HW     (IMG_H * IMG_W)
#define RENDER_SZ (3 * HW)
#define ALPHA_THRESH (1.0f / 255.0f)

#define NBLOCKS 148
#define NTHREADS 256
#define NWARPS_TOTAL (NBLOCKS * (NTHREADS / 32))   // 1184

// Persistent accumulator: zero at module load; phase 2 re-zeroes after
// consuming, so every replay sees zeros.
__device__ float g_accum[RENDER_SZ];
// Monotonic barrier counter (never reset; generation = count / gridDim).
__device__ unsigned g_bar;

__device__ __forceinline__ float sigmoidf_(float v) {
    return 1.0f / (1.0f + __expf(-v));
}

// Replay-safe grid barrier: counter only ever increments; each generation's
// release target is the next multiple of nblocks. All 148 blocks are
// co-resident (1 block/SM), so spinning cannot deadlock.
__device__ __forceinline__ void grid_barrier() {
    __syncthreads();
    if (threadIdx.x == 0) {
        __threadfence();                       // make prior atomics/stores visible
        unsigned arrival = atomicAdd(&g_bar, 1u);
        unsigned target = (arrival / NBLOCKS + 1u) * NBLOCKS;
        volatile unsigned* vb = &g_bar;
        while (*vb < target) { }
    }
    __syncthreads();
    __threadfence();                           // acquire side
}

__global__ void __launch_bounds__(NTHREADS, 1)
fused_kernel(const float* __restrict__ xyz,
             const float* __restrict__ cov2d,
             const float* __restrict__ fdc,
             const float* __restrict__ opac,
             const float* __restrict__ gfreq,
             const float* __restrict__ gwt,
             float* __restrict__ out, int out_size) {
    int lane = threadIdx.x & 31;
    int wg   = blockIdx.x * (NTHREADS / 32) + (threadIdx.x >> 5);  // global warp id

    // ---------------- Phase 1: scatter splat, one warp per Gaussian ----------
    for (int g = wg; g < NPTS; g += NWARPS_TOTAL) {
        // per-point prep (broadcast loads; identical in all lanes)
        float sxx = cov2d[3 * g + 0] + 0.5f;
        float sxy = cov2d[3 * g + 1];
        float syy = cov2d[3 * g + 2] + 0.5f;
        float det = sxx * syy - sxy * sxy;
        bool valid = det > 1e-8f;
        float det_s = valid ? det : 1.0f;
        float ca =  syy / det_s;
        float cb = -sxy / det_s;
        float cc =  sxx / det_s;

        float mid = 0.5f * (sxx + syy);
        float lam = mid + sqrtf(fmaxf(mid * mid - det, 0.1f));
        int radii = valid ? (int)ceilf(3.0f * sqrtf(lam)) : 0;

        if (lane == 0) {
            if (out_size >= RENDER_SZ + NPTS)
                out[RENDER_SZ + g] = (float)radii;
            if (out_size >= RENDER_SZ + 2 * NPTS)
                out[RENDER_SZ + NPTS + g] = (radii > 0) ? 1.0f : 0.0f;
        }

        float x  = xyz[2 * g + 0];
        float y  = xyz[2 * g + 1];
        float op = opac[g];

        // Support cutoff: alpha >= 1/255  <=>  sigma <= Tcut.
        float Tcut = __logf(fmaxf(op, 1e-30f) * 255.0f);
        if (!valid || Tcut <= 0.0f) continue;

        float cr  = sigmoidf_(fdc[3 * g + 0]);
        float cg  = sigmoidf_(fdc[3 * g + 1]);
        float cbl = sigmoidf_(fdc[3 * g + 2]);
        float fx0 = __expf(gfreq[(g * NGAB + 0) * 2 + 0]);
        float fy0 = __expf(gfreq[(g * NGAB + 0) * 2 + 1]);
        float fx1 = __expf(gfreq[(g * NGAB + 1) * 2 + 0]);
        float fy1 = __expf(gfreq[(g * NGAB + 1) * 2 + 1]);
        float w0  = sigmoidf_(gwt[g * NGAB + 0]);
        float w1  = sigmoidf_(gwt[g * NGAB + 1]);

        // Conservative bbox (superset of {alpha >= 1/255}) + 1px slop.
        float dxm = sqrtf(2.0f * Tcut * sxx) + 1.0f;
        float dym = sqrtf(2.0f * Tcut * syy) + 1.0f;
        int x0 = max(0, (int)floorf(x - dxm - 0.5f));
        int x1 = min(IMG_W - 1, (int)ceilf(x + dxm - 0.5f));
        int y0 = max(0, (int)floorf(y - dym - 0.5f));
        int y1 = min(IMG_H - 1, (int)ceilf(y + dym - 0.5f));
        int bw = x1 - x0 + 1;
        int bh = y1 - y0 + 1;
        if (bw <= 0 || bh <= 0) continue;
        int npix = bw * bh;

        for (int t = lane; t < npix; t += 32) {
            int px = x0 + (t % bw);
            int py = y0 + (t / bw);
            float dx = ((float)px + 0.5f) - x;
            float dy = ((float)py + 0.5f) - y;
            float sigma = 0.5f * (ca * dx * dx + cc * dy * dy) + cb * (dx * dy);
            float alpha = fminf(op * __expf(-sigma), 0.999f);
            if (alpha < ALPHA_THRESH) continue;   // exact reference threshold
            float arg0 = fx0 * dx + fy0 * dy;
            float arg1 = fx1 * dx + fy1 * dy;
            float mod = 1.0f + w0 * __cosf(arg0) + w1 * __cosf(arg1);
            float wgt = alpha * mod;
            int pix = py * IMG_W + px;
            atomicAdd(&g_accum[pix],          wgt * cr);
            atomicAdd(&g_accum[HW + pix],     wgt * cg);
            atomicAdd(&g_accum[2 * HW + pix], wgt * cbl);
        }
    }

    // ---------------- barrier: all atomics done & visible ----------------
    grid_barrier();

    // ---------------- Phase 2: clamp-sweep accum -> out, re-zero accum ----
    float4* acc4 = reinterpret_cast<float4*>(g_accum);
    float4* out4 = reinterpret_cast<float4*>(out);
    const int n4 = RENDER_SZ / 4;                  // 196608
    const int stride = NBLOCKS * NTHREADS;         // 37888
    const float4 z4 = make_float4(0.0f, 0.0f, 0.0f, 0.0f);
    for (int i = blockIdx.x * NTHREADS + threadIdx.x; i < n4; i += stride) {
        float4 v = acc4[i];
        v.x = fminf(fmaxf(v.x, 0.0f), 1.0f);
        v.y = fminf(fmaxf(v.y, 0.0f), 1.0f);
        v.z = fminf(fmaxf(v.z, 0.0f), 1.0f);
        v.w = fminf(fmaxf(v.w, 0.0f), 1.0f);
        out4[i] = v;
        acc4[i] = z4;
    }
}

extern "C" void kernel_launch(void* const* d_in, const int* in_sizes, int n_in,
                              void* d_out, int out_size) {
    const float* xyz   = (const float*)d_in[0];
    const float* cov2d = (const float*)d_in[1];
    const float* fdc   = (const float*)d_in[2];
    const float* opac  = (const float*)d_in[3];
    const float* gfreq = (const float*)d_in[4];
    const float* gwt   = (const float*)d_in[5];
    float* out = (float*)d_out;

    fused_kernel<<<NBLOCKS, NTHREADS>>>(xyz, cov2d, fdc, opac, gfreq, gwt, out, out_size);
}

// round 5
// speedup vs baseline: 2.6533x; 1.4365x over previous
#include <cuda_runtime.h>
#include <math.h>

#define NPTS   2048
#define NGAB   2
#define IMG_H  512
#define IMG_W  512
#define HW     (IMG_H * IMG_W)
#define RENDER_SZ (3 * HW)
#define ALPHA_THRESH (1.0f / 255.0f)

// Persistent accumulator. Zero at module load; finish re-zeroes touched
// entries after consuming, so every replay sees zeros.
__device__ float g_accum[RENDER_SZ];

__device__ __forceinline__ float sigmoidf_(float v) {
    return 1.0f / (1.0f + __expf(-v));
}

// One warp per Gaussian. All lanes redundantly run the tiny per-point prep
// from broadcast loads, then cooperatively splat the bbox with the exact
// reference alpha threshold applied per pixel.
__global__ void __launch_bounds__(128)
splat_kernel(const float* __restrict__ xyz,
             const float* __restrict__ cov2d,
             const float* __restrict__ fdc,
             const float* __restrict__ opac,
             const float* __restrict__ gfreq,
             const float* __restrict__ gwt,
             float* __restrict__ out, int out_size) {
    int g    = (blockIdx.x * blockDim.x + threadIdx.x) >> 5;
    int lane = threadIdx.x & 31;
    if (g >= NPTS) return;

    float sxx = cov2d[3 * g + 0] + 0.5f;
    float sxy = cov2d[3 * g + 1];
    float syy = cov2d[3 * g + 2] + 0.5f;
    float det = sxx * syy - sxy * sxy;
    bool valid = det > 1e-8f;
    float det_s = valid ? det : 1.0f;
    float ca =  syy / det_s;
    float cb = -sxy / det_s;
    float cc =  sxx / det_s;

    float mid = 0.5f * (sxx + syy);
    float lam = mid + sqrtf(fmaxf(mid * mid - det, 0.1f));
    int radii = valid ? (int)ceilf(3.0f * sqrtf(lam)) : 0;

    if (lane == 0) {
        if (out_size >= RENDER_SZ + NPTS)
            out[RENDER_SZ + g] = (float)radii;
        if (out_size >= RENDER_SZ + 2 * NPTS)
            out[RENDER_SZ + NPTS + g] = (radii > 0) ? 1.0f : 0.0f;
    }

    float x  = xyz[2 * g + 0];
    float y  = xyz[2 * g + 1];
    float op = opac[g];

    // Support cutoff: alpha >= 1/255  <=>  sigma <= Tcut.
    float Tcut = __logf(fmaxf(op, 1e-30f) * 255.0f);
    if (!valid || Tcut <= 0.0f) return;

    float cr  = sigmoidf_(fdc[3 * g + 0]);
    float cg  = sigmoidf_(fdc[3 * g + 1]);
    float cbl = sigmoidf_(fdc[3 * g + 2]);
    float fx0 = __expf(gfreq[(g * NGAB + 0) * 2 + 0]);
    float fy0 = __expf(gfreq[(g * NGAB + 0) * 2 + 1]);
    float fx1 = __expf(gfreq[(g * NGAB + 1) * 2 + 0]);
    float fy1 = __expf(gfreq[(g * NGAB + 1) * 2 + 1]);
    float w0  = sigmoidf_(gwt[g * NGAB + 0]);
    float w1  = sigmoidf_(gwt[g * NGAB + 1]);

    // Conservative bbox (superset of {alpha >= 1/255}) + 1px slop.
    float dxm = sqrtf(2.0f * Tcut * sxx) + 1.0f;
    float dym = sqrtf(2.0f * Tcut * syy) + 1.0f;
    int x0 = max(0, (int)floorf(x - dxm - 0.5f));
    int x1 = min(IMG_W - 1, (int)ceilf(x + dxm - 0.5f));
    int y0 = max(0, (int)floorf(y - dym - 0.5f));
    int y1 = min(IMG_H - 1, (int)ceilf(y + dym - 0.5f));
    int bw = x1 - x0 + 1;
    int bh = y1 - y0 + 1;
    if (bw <= 0 || bh <= 0) return;
    int npix = bw * bh;

    for (int t = lane; t < npix; t += 32) {
        int px = x0 + (t % bw);
        int py = y0 + (t / bw);
        float dx = ((float)px + 0.5f) - x;
        float dy = ((float)py + 0.5f) - y;
        float sigma = 0.5f * (ca * dx * dx + cc * dy * dy) + cb * (dx * dy);
        float alpha = fminf(op * __expf(-sigma), 0.999f);
        if (alpha < ALPHA_THRESH) continue;   // exact reference threshold
        float arg0 = fx0 * dx + fy0 * dy;
        float arg1 = fx1 * dx + fy1 * dy;
        float mod = 1.0f + w0 * __cosf(arg0) + w1 * __cosf(arg1);
        float wgt = alpha * mod;
        int pix = py * IMG_W + px;
        atomicAdd(&g_accum[pix],          wgt * cr);
        atomicAdd(&g_accum[HW + pix],     wgt * cg);
        atomicAdd(&g_accum[2 * HW + pix], wgt * cbl);
    }
}

// Read accum -> clamp -> write d_out; re-zero accum (only where nonzero).
// MLP=4: each thread owns 4 independent float4s to hide L2/DRAM latency.
#define FIN_ILP 4
#define FIN_THREADS 256
#define FIN_BLOCKS (RENDER_SZ / 4 / FIN_ILP / FIN_THREADS)   // 192

__global__ void __launch_bounds__(FIN_THREADS)
finish_kernel(float* __restrict__ out) {
    const int n4 = RENDER_SZ / 4;
    int base = blockIdx.x * FIN_THREADS + threadIdx.x;
    const int stride = FIN_BLOCKS * FIN_THREADS;     // 49152
    float4* acc4 = reinterpret_cast<float4*>(g_accum);
    float4* out4 = reinterpret_cast<float4*>(out);

    float4 v[FIN_ILP];
    int idx[FIN_ILP];
    #pragma unroll
    for (int k = 0; k < FIN_ILP; k++) {
        idx[k] = base + k * stride;                   // all < n4 by construction
        v[k] = acc4[idx[k]];
    }
    #pragma unroll
    for (int k = 0; k < FIN_ILP; k++) {
        float4 r = v[k];
        bool nz = (r.x != 0.0f) | (r.y != 0.0f) | (r.z != 0.0f) | (r.w != 0.0f);
        r.x = fminf(fmaxf(r.x, 0.0f), 1.0f);
        r.y = fminf(fmaxf(r.y, 0.0f), 1.0f);
        r.z = fminf(fmaxf(r.z, 0.0f), 1.0f);
        r.w = fminf(fmaxf(r.w, 0.0f), 1.0f);
        out4[idx[k]] = r;
        if (nz) acc4[idx[k]] = make_float4(0.0f, 0.0f, 0.0f, 0.0f);
    }
    (void)n4;
}

extern "C" void kernel_launch(void* const* d_in, const int* in_sizes, int n_in,
                              void* d_out, int out_size) {
    const float* xyz   = (const float*)d_in[0];
    const float* cov2d = (const float*)d_in[1];
    const float* fdc   = (const float*)d_in[2];
    const float* opac  = (const float*)d_in[3];
    const float* gfreq = (const float*)d_in[4];
    const float* gwt   = (const float*)d_in[5];
    float* out = (float*)d_out;

    splat_kernel<<<NPTS * 32 / 128, 128>>>(xyz, cov2d, fdc, opac, gfreq, gwt, out, out_size);
    finish_kernel<<<FIN_BLOCKS, FIN_THREADS>>>(out);
}